// round 1
// baseline (speedup 1.0000x reference)
#include <cuda_runtime.h>
#include <cuda_bf16.h>
#include <cstddef>

// Problem constants
#define BATCH 8
#define SEQ   1024
#define CDIM  768
#define HEADS 24
#define DHEAD 32
#define QKV_N (3*CDIM)          // 2304
#define ROWS  (BATCH*SEQ)       // 8192

// Scratch (allocation-free rule: __device__ globals)
__device__ float g_qkv[(size_t)ROWS * QKV_N];   // [B*N, 2304]
__device__ float g_att[(size_t)ROWS * CDIM];    // [B*N, 768]

// ---------------------------------------------------------------------------
// GEMM with bias:  C[m,n] = sum_k A[m,k] * W[n,k] + bias[n]
// BM=BN=64, BK=16, 256 threads, 4x4 per thread. All dims divide evenly here.
// ---------------------------------------------------------------------------
#define BM 64
#define BN 64
#define BK 16
#define SPAD 68   // padded row stride (floats), multiple of 4 -> float4 aligned

__global__ __launch_bounds__(256) void gemm_bias_kernel(
    const float* __restrict__ A, const float* __restrict__ W,
    const float* __restrict__ bias, float* __restrict__ C,
    int M, int N, int K)
{
    __shared__ float As[BK][SPAD];
    __shared__ float Bs[BK][SPAD];

    const int tx = threadIdx.x & 15;
    const int ty = threadIdx.x >> 4;
    const int m0 = blockIdx.y * BM;
    const int n0 = blockIdx.x * BN;

    float acc[4][4] = {};

    for (int k0 = 0; k0 < K; k0 += BK) {
        // cooperative tile load: each thread one float4 from A and one from W
        {
            const int t   = threadIdx.x;
            const int row = t >> 2;          // 0..63
            const int c4  = (t & 3) * 4;     // 0,4,8,12
            float4 a = *(const float4*)&A[(size_t)(m0 + row) * K + k0 + c4];
            As[c4 + 0][row] = a.x;
            As[c4 + 1][row] = a.y;
            As[c4 + 2][row] = a.z;
            As[c4 + 3][row] = a.w;
            float4 b = *(const float4*)&W[(size_t)(n0 + row) * K + k0 + c4];
            Bs[c4 + 0][row] = b.x;
            Bs[c4 + 1][row] = b.y;
            Bs[c4 + 2][row] = b.z;
            Bs[c4 + 3][row] = b.w;
        }
        __syncthreads();

        #pragma unroll
        for (int kk = 0; kk < BK; kk++) {
            float4 a4 = *(const float4*)&As[kk][ty * 4];
            float4 b4 = *(const float4*)&Bs[kk][tx * 4];
            float ar[4] = {a4.x, a4.y, a4.z, a4.w};
            float br[4] = {b4.x, b4.y, b4.z, b4.w};
            #pragma unroll
            for (int i = 0; i < 4; i++)
                #pragma unroll
                for (int j = 0; j < 4; j++)
                    acc[i][j] += ar[i] * br[j];
        }
        __syncthreads();
    }

    const float4 bv = *(const float4*)&bias[n0 + tx * 4];
    const float bb[4] = {bv.x, bv.y, bv.z, bv.w};
    #pragma unroll
    for (int i = 0; i < 4; i++) {
        const int m = m0 + ty * 4 + i;
        float4 o;
        o.x = acc[i][0] + bb[0];
        o.y = acc[i][1] + bb[1];
        o.z = acc[i][2] + bb[2];
        o.w = acc[i][3] + bb[3];
        *(float4*)&C[(size_t)m * N + n0 + tx * 4] = o;
    }
}

// ---------------------------------------------------------------------------
// Flash attention: one thread per query row, 128 query rows per block.
// K/V tiles (64 rows x 32 dims) staged in smem; bias streamed from gmem
// (per-thread linear rows -> sectors fully reused in L1).
// ---------------------------------------------------------------------------
#define QT 128
#define KT 64
#define KVPAD 36  // multiple of 4 -> aligned float4, decent bank spread

__global__ __launch_bounds__(128) void attn_kernel(
    const float* __restrict__ qkv,   // [B*N, 2304]
    const float* __restrict__ bias,  // [H, N, N]
    float* __restrict__ out)         // [B*N, 768]
{
    __shared__ float Ks[KT][KVPAD];
    __shared__ float Vs[KT][KVPAD];

    const int b = blockIdx.z;
    const int h = blockIdx.y;
    const int q = blockIdx.x * QT + threadIdx.x;   // 0..1023

    const float scale = 0.17677669529663687f;      // 1/sqrt(32)

    const float* qrow = qkv + ((size_t)(b * SEQ + q)) * QKV_N + h * 96;
    float qv[DHEAD];
    #pragma unroll
    for (int d = 0; d < DHEAD; d++) qv[d] = qrow[d] * scale;

    const float* brow = bias + ((size_t)h * SEQ + q) * SEQ;

    float acc[DHEAD] = {};
    float m = -1e30f, l = 0.0f;

    for (int k0 = 0; k0 < SEQ; k0 += KT) {
        // cooperative K/V tile load: 64 rows x 32 floats each
        {
            const int t = threadIdx.x;
            #pragma unroll
            for (int i = 0; i < 4; i++) {
                const int e  = t + i * 128;    // 0..511
                const int r  = e >> 3;         // 0..63
                const int d4 = (e & 7) * 4;    // 0..28
                const float* src = qkv + ((size_t)(b * SEQ + k0 + r)) * QKV_N + h * 96;
                *(float4*)&Ks[r][d4] = *(const float4*)(src + 32 + d4);
                *(float4*)&Vs[r][d4] = *(const float4*)(src + 64 + d4);
            }
        }
        __syncthreads();

        // scores for this tile
        float s[KT];
        #pragma unroll
        for (int j = 0; j < KT; j++) {
            float sum = 0.0f;
            #pragma unroll
            for (int d4 = 0; d4 < DHEAD; d4 += 4) {
                float4 k4 = *(const float4*)&Ks[j][d4];
                sum += qv[d4 + 0] * k4.x;
                sum += qv[d4 + 1] * k4.y;
                sum += qv[d4 + 2] * k4.z;
                sum += qv[d4 + 3] * k4.w;
            }
            s[j] = sum + brow[k0 + j];
        }

        // online softmax update
        float tmax = s[0];
        #pragma unroll
        for (int j = 1; j < KT; j++) tmax = fmaxf(tmax, s[j]);
        const float mnew = fmaxf(m, tmax);
        const float corr = __expf(m - mnew);
        l *= corr;
        #pragma unroll
        for (int d = 0; d < DHEAD; d++) acc[d] *= corr;

        #pragma unroll
        for (int j = 0; j < KT; j++) {
            const float p = __expf(s[j] - mnew);
            l += p;
            #pragma unroll
            for (int d4 = 0; d4 < DHEAD; d4 += 4) {
                float4 v4 = *(const float4*)&Vs[j][d4];
                acc[d4 + 0] += p * v4.x;
                acc[d4 + 1] += p * v4.y;
                acc[d4 + 2] += p * v4.z;
                acc[d4 + 3] += p * v4.w;
            }
        }
        m = mnew;
        __syncthreads();
    }

    const float inv = 1.0f / l;
    float* orow = out + ((size_t)(b * SEQ + q)) * CDIM + h * DHEAD;
    #pragma unroll
    for (int d4 = 0; d4 < DHEAD; d4 += 4) {
        float4 o;
        o.x = acc[d4 + 0] * inv;
        o.y = acc[d4 + 1] * inv;
        o.z = acc[d4 + 2] * inv;
        o.w = acc[d4 + 3] * inv;
        *(float4*)(orow + d4) = o;
    }
}

// ---------------------------------------------------------------------------
extern "C" void kernel_launch(void* const* d_in, const int* in_sizes, int n_in,
                              void* d_out, int out_size)
{
    const float* x      = (const float*)d_in[0];  // [B,N,C]
    const float* relpos = (const float*)d_in[1];  // [H,N,N]
    const float* Wqkv   = (const float*)d_in[2];  // [3C,C]
    const float* bqkv   = (const float*)d_in[3];  // [3C]
    const float* Wproj  = (const float*)d_in[4];  // [C,C]
    const float* bproj  = (const float*)d_in[5];  // [C]
    float* out = (float*)d_out;                   // [B,N,C]

    float *qkv = nullptr, *att = nullptr;
    cudaGetSymbolAddress((void**)&qkv, g_qkv);
    cudaGetSymbolAddress((void**)&att, g_att);

    // 1) QKV projection: [8192,768] @ [2304,768]^T + b -> [8192,2304]
    gemm_bias_kernel<<<dim3(QKV_N / BN, ROWS / BM), 256>>>(
        x, Wqkv, bqkv, qkv, ROWS, QKV_N, CDIM);

    // 2) fused attention -> [8192,768] (head-interleaved, proj-ready)
    attn_kernel<<<dim3(SEQ / QT, HEADS, BATCH), QT>>>(qkv, relpos, att);

    // 3) output projection: [8192,768] @ [768,768]^T + b
    gemm_bias_kernel<<<dim3(CDIM / BN, ROWS / BM), 256>>>(
        att, Wproj, bproj, out, ROWS, CDIM, CDIM);
}

// round 2
// speedup vs baseline: 1.3607x; 1.3607x over previous
#include <cuda_runtime.h>
#include <cuda_bf16.h>
#include <cstddef>

// Problem constants
#define BATCH 8
#define SEQ   1024
#define CDIM  768
#define HEADS 24
#define DHEAD 32
#define QKV_N (3*CDIM)          // 2304
#define ROWS  (BATCH*SEQ)       // 8192

// Scratch (allocation-free rule: __device__ globals)
__device__ float g_qkv[(size_t)ROWS * QKV_N];   // [B*N, 2304]
__device__ float g_att[(size_t)ROWS * CDIM];    // [B*N, 768]

// ---------------------------------------------------------------------------
// GEMM with bias:  C[m,n] = sum_k A[m,k] * W[n,k] + bias[n]
// 128x128 tile, BK=16, 256 threads, 8x8 per thread.
// ---------------------------------------------------------------------------
#define GM 128
#define GN 128
#define GK 16

__global__ __launch_bounds__(256) void gemm_bias_kernel(
    const float* __restrict__ A, const float* __restrict__ W,
    const float* __restrict__ bias, float* __restrict__ C,
    int M, int N, int K)
{
    __shared__ float As[GK][GM];   // k-major
    __shared__ float Bs[GK][GN];

    const int t  = threadIdx.x;
    const int tx = t & 15;          // 0..15 -> n
    const int ty = t >> 4;          // 0..15 -> m
    const int m0 = blockIdx.y * GM;
    const int n0 = blockIdx.x * GN;

    float acc[8][8] = {};
    float ar[8], br[8];

    for (int k0 = 0; k0 < K; k0 += GK) {
        // load A tile (128x16) and B tile (128x16), transpose into k-major smem
        #pragma unroll
        for (int i = 0; i < 2; i++) {
            const int f   = t + i * 256;   // 0..511
            const int row = f >> 2;        // 0..127
            const int c4  = (f & 3) * 4;   // 0,4,8,12
            float4 a = *(const float4*)&A[(size_t)(m0 + row) * K + k0 + c4];
            As[c4 + 0][row] = a.x;
            As[c4 + 1][row] = a.y;
            As[c4 + 2][row] = a.z;
            As[c4 + 3][row] = a.w;
            float4 b = *(const float4*)&W[(size_t)(n0 + row) * K + k0 + c4];
            Bs[c4 + 0][row] = b.x;
            Bs[c4 + 1][row] = b.y;
            Bs[c4 + 2][row] = b.z;
            Bs[c4 + 3][row] = b.w;
        }
        __syncthreads();

        #pragma unroll
        for (int kk = 0; kk < GK; kk++) {
            *(float4*)&ar[0] = *(const float4*)&As[kk][ty * 8 + 0];
            *(float4*)&ar[4] = *(const float4*)&As[kk][ty * 8 + 4];
            *(float4*)&br[0] = *(const float4*)&Bs[kk][tx * 8 + 0];
            *(float4*)&br[4] = *(const float4*)&Bs[kk][tx * 8 + 4];
            #pragma unroll
            for (int i = 0; i < 8; i++)
                #pragma unroll
                for (int j = 0; j < 8; j++)
                    acc[i][j] += ar[i] * br[j];
        }
        __syncthreads();
    }

    float bb[8];
    *(float4*)&bb[0] = *(const float4*)&bias[n0 + tx * 8 + 0];
    *(float4*)&bb[4] = *(const float4*)&bias[n0 + tx * 8 + 4];
    #pragma unroll
    for (int i = 0; i < 8; i++) {
        const int m = m0 + ty * 8 + i;
        float4 o0, o1;
        o0.x = acc[i][0] + bb[0]; o0.y = acc[i][1] + bb[1];
        o0.z = acc[i][2] + bb[2]; o0.w = acc[i][3] + bb[3];
        o1.x = acc[i][4] + bb[4]; o1.y = acc[i][5] + bb[5];
        o1.z = acc[i][6] + bb[6]; o1.w = acc[i][7] + bb[7];
        *(float4*)&C[(size_t)m * N + n0 + tx * 8 + 0] = o0;
        *(float4*)&C[(size_t)m * N + n0 + tx * 8 + 4] = o1;
    }
}

// ---------------------------------------------------------------------------
// Flash attention: one thread per query row, 128 query rows per block.
// KT=32 keeps registers bounded (qv[32]+acc[32]+s[32] ~ 120 regs, no spill).
// K/V tiles in smem (score loads are warp-broadcast); bias via float4.
// ---------------------------------------------------------------------------
#define QT 128
#define KT 32
#define KVPAD 36

__global__ __launch_bounds__(128) void attn_kernel(
    const float* __restrict__ qkv,   // [B*N, 2304]
    const float* __restrict__ bias,  // [H, N, N]
    float* __restrict__ out)         // [B*N, 768]
{
    __shared__ float Ks[KT][KVPAD];
    __shared__ float Vs[KT][KVPAD];

    const int b = blockIdx.z;
    const int h = blockIdx.y;
    const int q = blockIdx.x * QT + threadIdx.x;   // 0..1023

    const float scale = 0.17677669529663687f;      // 1/sqrt(32)

    const float* qrow = qkv + ((size_t)(b * SEQ + q)) * QKV_N + h * 96;
    float qv[DHEAD];
    #pragma unroll
    for (int d4 = 0; d4 < DHEAD; d4 += 4) {
        float4 v = *(const float4*)(qrow + d4);
        qv[d4 + 0] = v.x * scale;
        qv[d4 + 1] = v.y * scale;
        qv[d4 + 2] = v.z * scale;
        qv[d4 + 3] = v.w * scale;
    }

    const float* brow = bias + ((size_t)h * SEQ + q) * SEQ;

    float acc[DHEAD] = {};
    float m = -1e30f, l = 0.0f;

    for (int k0 = 0; k0 < SEQ; k0 += KT) {
        // cooperative K/V tile load: 32 rows x 32 floats each
        {
            const int t = threadIdx.x;
            #pragma unroll
            for (int i = 0; i < 2; i++) {
                const int e  = t + i * 128;    // 0..255
                const int r  = e >> 3;         // 0..31
                const int d4 = (e & 7) * 4;    // 0..28
                const float* src = qkv + ((size_t)(b * SEQ + k0 + r)) * QKV_N + h * 96;
                *(float4*)&Ks[r][d4] = *(const float4*)(src + 32 + d4);
                *(float4*)&Vs[r][d4] = *(const float4*)(src + 64 + d4);
            }
        }
        __syncthreads();

        // scores for this tile (bias read as float4)
        float s[KT];
        #pragma unroll
        for (int j4 = 0; j4 < KT / 4; j4++) {
            float4 b4 = *(const float4*)&brow[k0 + j4 * 4];
            float bf[4] = {b4.x, b4.y, b4.z, b4.w};
            #pragma unroll
            for (int u = 0; u < 4; u++) {
                const int j = j4 * 4 + u;
                float sum = 0.0f;
                #pragma unroll
                for (int d4 = 0; d4 < DHEAD; d4 += 4) {
                    float4 k4 = *(const float4*)&Ks[j][d4];
                    sum += qv[d4 + 0] * k4.x;
                    sum += qv[d4 + 1] * k4.y;
                    sum += qv[d4 + 2] * k4.z;
                    sum += qv[d4 + 3] * k4.w;
                }
                s[j] = sum + bf[u];
            }
        }

        // online softmax update
        float tmax = s[0];
        #pragma unroll
        for (int j = 1; j < KT; j++) tmax = fmaxf(tmax, s[j]);
        const float mnew = fmaxf(m, tmax);
        const float corr = __expf(m - mnew);
        l *= corr;
        #pragma unroll
        for (int d = 0; d < DHEAD; d++) acc[d] *= corr;

        #pragma unroll
        for (int j = 0; j < KT; j++) {
            const float p = __expf(s[j] - mnew);
            l += p;
            #pragma unroll
            for (int d4 = 0; d4 < DHEAD; d4 += 4) {
                float4 v4 = *(const float4*)&Vs[j][d4];
                acc[d4 + 0] += p * v4.x;
                acc[d4 + 1] += p * v4.y;
                acc[d4 + 2] += p * v4.z;
                acc[d4 + 3] += p * v4.w;
            }
        }
        m = mnew;
        __syncthreads();
    }

    const float inv = 1.0f / l;
    float* orow = out + ((size_t)(b * SEQ + q)) * CDIM + h * DHEAD;
    #pragma unroll
    for (int d4 = 0; d4 < DHEAD; d4 += 4) {
        float4 o;
        o.x = acc[d4 + 0] * inv;
        o.y = acc[d4 + 1] * inv;
        o.z = acc[d4 + 2] * inv;
        o.w = acc[d4 + 3] * inv;
        *(float4*)(orow + d4) = o;
    }
}

// ---------------------------------------------------------------------------
extern "C" void kernel_launch(void* const* d_in, const int* in_sizes, int n_in,
                              void* d_out, int out_size)
{
    const float* x      = (const float*)d_in[0];  // [B,N,C]
    const float* relpos = (const float*)d_in[1];  // [H,N,N]
    const float* Wqkv   = (const float*)d_in[2];  // [3C,C]
    const float* bqkv   = (const float*)d_in[3];  // [3C]
    const float* Wproj  = (const float*)d_in[4];  // [C,C]
    const float* bproj  = (const float*)d_in[5];  // [C]
    float* out = (float*)d_out;                   // [B,N,C]

    float *qkv = nullptr, *att = nullptr;
    cudaGetSymbolAddress((void**)&qkv, g_qkv);
    cudaGetSymbolAddress((void**)&att, g_att);

    // 1) QKV projection: [8192,768] @ [2304,768]^T + b -> [8192,2304]
    gemm_bias_kernel<<<dim3(QKV_N / GN, ROWS / GM), 256>>>(
        x, Wqkv, bqkv, qkv, ROWS, QKV_N, CDIM);

    // 2) fused attention -> [8192,768] (head-interleaved, proj-ready)
    attn_kernel<<<dim3(SEQ / QT, HEADS, BATCH), QT>>>(qkv, relpos, att);

    // 3) output projection: [8192,768] @ [768,768]^T + b
    gemm_bias_kernel<<<dim3(CDIM / GN, ROWS / GM), 256>>>(
        att, Wproj, bproj, out, ROWS, CDIM, CDIM);
}